// round 14
// baseline (speedup 1.0000x reference)
#include <cuda_runtime.h>
#include <cuda_bf16.h>
#include <cstdint>

// ChannelPruner: out[b,o,h,w] = sum_c w[o,c] * x[b,c,h,w]
// x: (32, 256, 56, 56) fp32, w: (256, 256, 1, 1) fp32.
// Fused generic sparse-row kernel (correct for ANY w), R1 launch shape
// (8192 blocks x 256 thr). New: the output plane is staged in shared memory
// and written with ONE cp.async.bulk (TMA 1D) store of 12544 contiguous
// bytes per CTA — replacing 784 scattered STG.128s with a single large
// burst, bypassing L1 on the write path.

#define N_CH   256
#define HW4    784            // 56*56/4 float4 per plane
#define NBATCH 32
#define PLANE_BYTES (HW4 * 16)   // 12544 = 98 * 128B

__global__ __launch_bounds__(256, 8)
void channel_pruner_kernel(const float4* __restrict__ X,
                           const float4* __restrict__ W,   // row o = W[o*64 .. o*64+63]
                           float4* __restrict__ O)
{
    const int o   = blockIdx.x;    // output channel
    const int b   = blockIdx.y;    // batch
    const int tid = threadIdx.x;   // 256 threads

    __shared__ int    s_cnt[64];
    __shared__ int    s_off[64];
    __shared__ int    s_nnz;
    __shared__ int    s_c[N_CH];
    __shared__ float  s_v[N_CH];
    __shared__ __align__(128) float4 s_plane[HW4];   // 12544 B staging buffer

    // --- Phase 1: cooperative scan of w row o (64 float4 = 256 floats) ---
    float4 w4;
    int myCnt = 0;
    if (tid < 64) {
        w4 = __ldg(&W[o * 64 + tid]);
        myCnt = (w4.x != 0.0f) + (w4.y != 0.0f) + (w4.z != 0.0f) + (w4.w != 0.0f);
        s_cnt[tid] = myCnt;
    }
    __syncthreads();

    if (tid == 0) {
        int run = 0;
        #pragma unroll
        for (int i = 0; i < 64; i++) { s_off[i] = run; run += s_cnt[i]; }
        s_nnz = run;
    }
    __syncthreads();

    if (tid < 64 && myCnt > 0) {
        int p = s_off[tid];
        const int cbase = tid * 4;
        if (w4.x != 0.0f) { s_c[p] = cbase + 0; s_v[p] = w4.x; p++; }
        if (w4.y != 0.0f) { s_c[p] = cbase + 1; s_v[p] = w4.y; p++; }
        if (w4.z != 0.0f) { s_c[p] = cbase + 2; s_v[p] = w4.z; p++; }
        if (w4.w != 0.0f) { s_c[p] = cbase + 3; s_v[p] = w4.w; p++; }
    }
    __syncthreads();

    const int nnz = s_nnz;
    const size_t planeStride = (size_t)N_CH * HW4;
    const float4* __restrict__ Xb = X + (size_t)b * planeStride;
    float4* __restrict__ Ob = O + (size_t)b * planeStride + (size_t)o * HW4;

    // --- Phase 2: compute the plane into smem ---
    if (nnz == 0) {
        const float4 z = make_float4(0.f, 0.f, 0.f, 0.f);
        s_plane[tid]       = z;
        s_plane[tid + 256] = z;
        s_plane[tid + 512] = z;
        if (tid < HW4 - 768) s_plane[tid + 768] = z;
    } else if (nnz == 1) {
        const float v = s_v[0];
        const float4* __restrict__ Xc = Xb + (size_t)s_c[0] * HW4;
        // 784 = 3*256 + 16: all loads issued before any store (MLP 3-4)
        float4 a0 = __ldg(&Xc[tid]);
        float4 a1 = __ldg(&Xc[tid + 256]);
        float4 a2 = __ldg(&Xc[tid + 512]);
        float4 a3;
        if (tid < HW4 - 768) a3 = __ldg(&Xc[tid + 768]);
        a0.x *= v; a0.y *= v; a0.z *= v; a0.w *= v;
        a1.x *= v; a1.y *= v; a1.z *= v; a1.w *= v;
        a2.x *= v; a2.y *= v; a2.z *= v; a2.w *= v;
        s_plane[tid]       = a0;
        s_plane[tid + 256] = a1;
        s_plane[tid + 512] = a2;
        if (tid < HW4 - 768) {
            a3.x *= v; a3.y *= v; a3.z *= v; a3.w *= v;
            s_plane[tid + 768] = a3;
        }
    } else {
        for (int s = tid; s < HW4; s += 256) {
            float4 acc = make_float4(0.f, 0.f, 0.f, 0.f);
            for (int k = 0; k < nnz; k++) {
                const float v = s_v[k];
                const float4 xv = __ldg(&Xb[(size_t)s_c[k] * HW4 + s]);
                acc.x += v * xv.x;
                acc.y += v * xv.y;
                acc.z += v * xv.z;
                acc.w += v * xv.w;
            }
            s_plane[s] = acc;
        }
    }
    __syncthreads();

    // --- Phase 3: one bulk store of the whole plane (smem -> gmem) ---
    if (tid == 0) {
        uint32_t saddr = (uint32_t)__cvta_generic_to_shared(s_plane);
        // order generic-proxy smem writes before the async-proxy bulk read
        asm volatile("fence.proxy.async.shared::cta;" ::: "memory");
        asm volatile(
            "cp.async.bulk.global.shared::cta.bulk_group [%0], [%1], %2;"
            :: "l"(Ob), "r"(saddr), "n"(PLANE_BYTES) : "memory");
        asm volatile("cp.async.bulk.commit_group;" ::: "memory");
        asm volatile("cp.async.bulk.wait_group 0;" ::: "memory");
    }
    // CTA may not exit before the bulk store has consumed smem; the
    // wait_group above guarantees completion for the issuing thread, and
    // the other threads have no further smem writes.
}

extern "C" void kernel_launch(void* const* d_in, const int* in_sizes, int n_in,
                              void* d_out, int out_size)
{
    const float4* X = (const float4*)d_in[0];   // x: 32*256*56*56 fp32
    const float4* W = (const float4*)d_in[1];   // conv_weights: 256*256*1*1 fp32
    float4* O = (float4*)d_out;

    dim3 grid(N_CH, NBATCH);    // 8192 blocks: one per (b, o) plane
    channel_pruner_kernel<<<grid, 256>>>(X, W, O);
}

// round 15
// speedup vs baseline: 1.1559x; 1.1559x over previous
#include <cuda_runtime.h>
#include <cuda_bf16.h>

// ChannelPruner: out[b,o,h,w] = sum_c w[o,c] * x[b,c,h,w]
// x: (32, 256, 56, 56) fp32, w: (256, 256, 1, 1) fp32.
// Fused generic sparse-row kernel (correct for ANY w), R1 launch shape
// (8192 blocks x 256 thr, measured best). This round: warp-local row
// compaction — each warp redundantly compacts w[o,:] into its own smem
// slice via shfl-scan. NO __syncthreads anywhere: each warp begins its
// memory stream as soon as its own (cheap) scan completes.

#define N_CH   256
#define HW4    784          // 56*56/4 float4 per plane
#define NBATCH 32

__global__ __launch_bounds__(256, 8)
void channel_pruner_kernel(const float4* __restrict__ X,
                           const float4* __restrict__ W,   // row o = W[o*64 .. o*64+63]
                           float4* __restrict__ O)
{
    const int o    = blockIdx.x;    // output channel
    const int b    = blockIdx.y;    // batch
    const int tid  = threadIdx.x;   // 256 threads
    const int wid  = tid >> 5;      // warp 0..7
    const int lane = tid & 31;

    // per-warp private compaction slices (8 warps x 256 entries)
    __shared__ int   s_c[8][N_CH];
    __shared__ float s_v[8][N_CH];

    // --- Phase 1: warp-local scan of w row o (each warp does the full row) ---
    // lane l owns float4 indices {2l, 2l+1} = channels 8l..8l+7 (contiguous,
    // so the compacted array is channel-sorted and deterministic).
    const float4 wa = __ldg(&W[o * 64 + lane * 2]);
    const float4 wb = __ldg(&W[o * 64 + lane * 2 + 1]);
    const int cnt = (wa.x != 0.0f) + (wa.y != 0.0f) + (wa.z != 0.0f) + (wa.w != 0.0f)
                  + (wb.x != 0.0f) + (wb.y != 0.0f) + (wb.z != 0.0f) + (wb.w != 0.0f);

    // warp-inclusive scan of cnt
    int incl = cnt;
    #pragma unroll
    for (int d = 1; d < 32; d <<= 1) {
        int t = __shfl_up_sync(0xFFFFFFFFu, incl, d);
        if (lane >= d) incl += t;
    }
    const int nnz  = __shfl_sync(0xFFFFFFFFu, incl, 31);
    int p = incl - cnt;                       // exclusive offset

    if (cnt > 0) {
        const int cbase = lane * 8;
        int*   wc = s_c[wid];
        float* wv = s_v[wid];
        if (wa.x != 0.0f) { wc[p] = cbase + 0; wv[p] = wa.x; p++; }
        if (wa.y != 0.0f) { wc[p] = cbase + 1; wv[p] = wa.y; p++; }
        if (wa.z != 0.0f) { wc[p] = cbase + 2; wv[p] = wa.z; p++; }
        if (wa.w != 0.0f) { wc[p] = cbase + 3; wv[p] = wa.w; p++; }
        if (wb.x != 0.0f) { wc[p] = cbase + 4; wv[p] = wb.x; p++; }
        if (wb.y != 0.0f) { wc[p] = cbase + 5; wv[p] = wb.y; p++; }
        if (wb.z != 0.0f) { wc[p] = cbase + 6; wv[p] = wb.z; p++; }
        if (wb.w != 0.0f) { wc[p] = cbase + 7; wv[p] = wb.w; p++; }
    }
    __syncwarp();   // warp-local visibility of its own slice; no block barrier

    const int*   wc = s_c[wid];
    const float* wv = s_v[wid];

    const size_t planeStride = (size_t)N_CH * HW4;
    const float4* __restrict__ Xb = X + (size_t)b * planeStride;
    float4* __restrict__ Ob = O + (size_t)b * planeStride + (size_t)o * HW4;

    // --- Phase 2: stream the plane (each warp independent) ---
    if (nnz == 0) {
        const float4 z = make_float4(0.f, 0.f, 0.f, 0.f);
        Ob[tid]       = z;
        Ob[tid + 256] = z;
        Ob[tid + 512] = z;
        if (tid < HW4 - 768) Ob[tid + 768] = z;
    } else if (nnz == 1) {
        const float v = wv[0];
        const float4* __restrict__ Xc = Xb + (size_t)wc[0] * HW4;
        // 784 = 3*256 + 16: all loads issued before any store (MLP 3-4)
        float4 a0 = __ldg(&Xc[tid]);
        float4 a1 = __ldg(&Xc[tid + 256]);
        float4 a2 = __ldg(&Xc[tid + 512]);
        float4 a3;
        if (tid < HW4 - 768) a3 = __ldg(&Xc[tid + 768]);
        a0.x *= v; a0.y *= v; a0.z *= v; a0.w *= v;
        a1.x *= v; a1.y *= v; a1.z *= v; a1.w *= v;
        a2.x *= v; a2.y *= v; a2.z *= v; a2.w *= v;
        Ob[tid]       = a0;
        Ob[tid + 256] = a1;
        Ob[tid + 512] = a2;
        if (tid < HW4 - 768) {
            a3.x *= v; a3.y *= v; a3.z *= v; a3.w *= v;
            Ob[tid + 768] = a3;
        }
    } else {
        // generic sparse accumulation (indices/values are warp-private smem)
        for (int s = tid; s < HW4; s += 256) {
            float4 acc = make_float4(0.f, 0.f, 0.f, 0.f);
            for (int k = 0; k < nnz; k++) {
                const float v = wv[k];
                const float4 xv = __ldg(&Xb[(size_t)wc[k] * HW4 + s]);
                acc.x += v * xv.x;
                acc.y += v * xv.y;
                acc.z += v * xv.z;
                acc.w += v * xv.w;
            }
            Ob[s] = acc;
        }
    }
}

extern "C" void kernel_launch(void* const* d_in, const int* in_sizes, int n_in,
                              void* d_out, int out_size)
{
    const float4* X = (const float4*)d_in[0];   // x: 32*256*56*56 fp32
    const float4* W = (const float4*)d_in[1];   // conv_weights: 256*256*1*1 fp32
    float4* O = (float4*)d_out;

    dim3 grid(N_CH, NBATCH);    // 8192 blocks: one per (b, o) plane
    channel_pruner_kernel<<<grid, 256>>>(X, W, O);
}